// round 6
// baseline (speedup 1.0000x reference)
#include <cuda_runtime.h>
#include <math.h>

#define Bsz   256
#define Tlen  1024
#define Hdim  128
#define NBLK  128      // 8 batch-tiles x 16 unit-tiles
#define NTHR  256
#define MT    32       // batches per CTA
#define UT    8        // hidden units per CTA (x4 gates = 32 rows)
#define KP1   129
#define KP2   257
#define KP3   385

// ---- shared memory layout (float offsets) ----
#define OFF_W1 0
#define OFF_W2 (OFF_W1 + KP1*32)        // 4128
#define OFF_W3 (OFF_W2 + KP2*32)        // 12352
#define OFF_A  (OFF_W3 + KP3*32)        // 24672  activations [k][m], k: 0=x,1..128=h1,129..256=h2,257..384=h3
#define OFF_G  (OFF_A  + KP3*32)        // 36992  gates [32 rows][32 m]
#define OFF_C  (OFF_G  + 32*32)         // 38016  c state [3][8][32]
#define OFF_BS (OFF_C  + 3*UT*32)       // 38784  combined biases [3][32]
#define OFF_WL (OFF_BS + 3*32)          // 38880  W_lin [385] (+pad)
#define OFF_OP (OFF_WL + 388)           // 39268  o partials [8][32]
#define OFF_BL (OFF_OP + 8*32)          // 39524  b_lin
#define SMEM_FLOATS (OFF_BL + 4)        // 39528
#define SMEM_BYTES  (SMEM_FLOATS*4)     // 158112 bytes -> 1 CTA/SM

// ---- global scratch (device globals: no allocation) ----
__device__ float    g_h[3][Hdim][Bsz];  // [layer][unit][batch]
__device__ unsigned g_cnt = 0;
__device__ unsigned g_gen = 0;

__device__ __forceinline__ void grid_barrier()
{
    __threadfence();          // publish this thread's global writes
    __syncthreads();          // everyone's writes fenced before arrival
    if (threadIdx.x == 0) {
        volatile unsigned* vgen = &g_gen;
        unsigned target = *vgen + 1;      // safe: barrier cannot complete without us
        unsigned old = atomicAdd(&g_cnt, 1);
        if (old == NBLK - 1) {
            *((volatile unsigned*)&g_cnt) = 0;
            __threadfence();              // cnt reset visible before gen flip
            *vgen = target;
        } else {
            while (*vgen != target) { }
        }
        __threadfence();
    }
    __syncthreads();
}

// 32x32 gate tile GEMM: lane = batch m, warp wi owns rows 4wi..4wi+3.
// a[k][m] conflict-free LDS.32, w[k][4wi..] broadcast LDS.128.
template<int K>
__device__ __forceinline__ void gemm32(const float* __restrict__ w,
                                       const float* __restrict__ a,
                                       int lane, int wi,
                                       float* __restrict__ gsh)
{
    float s0 = 0.f, s1 = 0.f, s2 = 0.f, s3 = 0.f;
    const float* ap = a + lane;
    const float* wp = w + 4*wi;
#pragma unroll 4
    for (int k = 0; k < K; k++) {
        float  av = ap[k*32];
        float4 wv = *reinterpret_cast<const float4*>(wp + k*32);
        s0 = fmaf(av, wv.x, s0);
        s1 = fmaf(av, wv.y, s1);
        s2 = fmaf(av, wv.z, s2);
        s3 = fmaf(av, wv.w, s3);
    }
    int r = 4*wi;
    gsh[(r+0)*32 + lane] = s0;
    gsh[(r+1)*32 + lane] = s1;
    gsh[(r+2)*32 + lane] = s2;
    gsh[(r+3)*32 + lane] = s3;
}

__device__ __forceinline__ float sigm(float v) { return 1.f / (1.f + expf(-v)); }

// per (u, m): read 4 gates, update c (CTA-private), write h to global
__device__ __forceinline__ void cell_update(int layer, int u, int m, int nt, int m0,
                                            const float* __restrict__ gsh,
                                            const float* __restrict__ bs,
                                            float* __restrict__ csh,
                                            float* __restrict__ hglob)
{
    float xi = gsh[( 0 + u)*32 + m] + bs[ 0 + u];
    float xf = gsh[( 8 + u)*32 + m] + bs[ 8 + u];
    float xg = gsh[(16 + u)*32 + m] + bs[16 + u];
    float xo = gsh[(24 + u)*32 + m] + bs[24 + u];
    float ii = sigm(xi);
    float ff = sigm(xf);
    float gg = tanhf(xg);
    float oo = sigm(xo);
    float* cp = csh + layer*(UT*32) + u*32 + m;
    float c = ff * cp[0] + ii * gg;
    cp[0] = c;
    float h = oo * tanhf(c);
    hglob[(nt*UT + u)*Bsz + m0 + m] = h;
}

__global__ void __launch_bounds__(NTHR, 1)
lstm_forecast_kernel(const float* __restrict__ x,
                     const float* __restrict__ Wih1, const float* __restrict__ Whh1,
                     const float* __restrict__ bih1, const float* __restrict__ bhh1,
                     const float* __restrict__ Wih2, const float* __restrict__ Whh2,
                     const float* __restrict__ bih2, const float* __restrict__ bhh2,
                     const float* __restrict__ Wih3, const float* __restrict__ Whh3,
                     const float* __restrict__ bih3, const float* __restrict__ bhh3,
                     const float* __restrict__ Wlin, const float* __restrict__ blin,
                     float* __restrict__ out, int fut)
{
    extern __shared__ float sm[];
    const int tid  = threadIdx.x;
    const int lane = tid & 31;
    const int wi   = tid >> 5;
    const int mt   = blockIdx.x >> 4;   // 0..7  batch tile
    const int nt   = blockIdx.x & 15;   // 0..15 unit tile
    const int m0   = mt * MT;

    float* w1  = sm + OFF_W1;
    float* w2  = sm + OFF_W2;
    float* w3  = sm + OFF_W3;
    float* ash = sm + OFF_A;
    float* gsh = sm + OFF_G;
    float* csh = sm + OFF_C;
    float* bsh = sm + OFF_BS;
    float* wls = sm + OFF_WL;
    float* ops = sm + OFF_OP;

    // ---------------- prologue: load transposed weight slices (once) ----------------
    for (int idx = tid; idx < 32*KP1; idx += NTHR) {
        int rl = idx & 31, k = idx >> 5;
        int rg = (rl >> 3)*Hdim + nt*UT + (rl & 7);
        w1[k*32 + rl] = (k < 1) ? Wih1[rg] : Whh1[rg*Hdim + (k - 1)];
    }
    for (int idx = tid; idx < 32*KP2; idx += NTHR) {
        int rl = idx & 31, k = idx >> 5;
        int rg = (rl >> 3)*Hdim + nt*UT + (rl & 7);
        w2[k*32 + rl] = (k < KP1) ? Wih2[rg*KP1 + k] : Whh2[rg*Hdim + (k - KP1)];
    }
    for (int idx = tid; idx < 32*KP3; idx += NTHR) {
        int rl = idx & 31, k = idx >> 5;
        int rg = (rl >> 3)*Hdim + nt*UT + (rl & 7);
        w3[k*32 + rl] = (k < KP2) ? Wih3[rg*KP2 + k] : Whh3[rg*Hdim + (k - KP2)];
    }
    if (tid < 32) {
        int rl = tid;
        int rg = (rl >> 3)*Hdim + nt*UT + (rl & 7);
        bsh[0*32 + rl] = bih1[rg] + bhh1[rg];
        bsh[1*32 + rl] = bih2[rg] + bhh2[rg];
        bsh[2*32 + rl] = bih3[rg] + bhh3[rg];
    }
    for (int idx = tid; idx < KP3; idx += NTHR) wls[idx] = Wlin[idx];
    if (tid == 0) sm[OFF_BL] = blin[0];
    for (int idx = tid; idx < KP3*32;  idx += NTHR) ash[idx] = 0.f;   // h(-1) = 0
    for (int idx = tid; idx < 3*UT*32; idx += NTHR) csh[idx] = 0.f;   // c(-1) = 0
    __syncthreads();

    const int Ttot = Tlen + fut;
    const int u = wi;     // update mapping: (unit u, batch lane)
    const int m = lane;

    for (int t = 0; t < Ttot; t++) {
        // x slot: real input for t < T, otherwise fed-back o from previous step
        if (t < Tlen) {
            if (tid < 32) ash[tid] = x[(m0 + tid)*Tlen + t];
        }
        __syncthreads();

        // ---------- layer 1 ----------
        gemm32<KP1>(w1, ash, lane, wi, gsh);
        __syncthreads();
        cell_update(0, u, m, nt, m0, gsh, bsh + 0,  csh, &g_h[0][0][0]);
        grid_barrier();
        {
            float* ah = ash + 1*32;
            const float* hg = &g_h[0][0][0];
#pragma unroll
            for (int i = tid; i < Hdim*32; i += NTHR)
                ah[i] = __ldcg(hg + (i >> 5)*Bsz + m0 + (i & 31));
        }
        __syncthreads();

        // ---------- layer 2 ----------
        gemm32<KP2>(w2, ash, lane, wi, gsh);
        __syncthreads();
        cell_update(1, u, m, nt, m0, gsh, bsh + 32, csh, &g_h[1][0][0]);
        grid_barrier();
        {
            float* ah = ash + KP1*32;
            const float* hg = &g_h[1][0][0];
#pragma unroll
            for (int i = tid; i < Hdim*32; i += NTHR)
                ah[i] = __ldcg(hg + (i >> 5)*Bsz + m0 + (i & 31));
        }
        __syncthreads();

        // ---------- layer 3 ----------
        gemm32<KP3>(w3, ash, lane, wi, gsh);
        __syncthreads();
        cell_update(2, u, m, nt, m0, gsh, bsh + 64, csh, &g_h[2][0][0]);
        grid_barrier();
        {
            float* ah = ash + KP2*32;
            const float* hg = &g_h[2][0][0];
#pragma unroll
            for (int i = tid; i < Hdim*32; i += NTHR)
                ah[i] = __ldcg(hg + (i >> 5)*Bsz + m0 + (i & 31));
        }
        __syncthreads();

        // ---------- linear head: o = [x,h1,h2,h3] . W_lin + b ----------
        // nt==0 writes output; every CTA computes o when it must feed back as x.
        bool doo = (nt == 0) || (t >= Tlen - 1);
        if (doo) {
            float p = 0.f;
            for (int k = wi; k < KP3; k += 8)
                p = fmaf(wls[k], ash[k*32 + lane], p);
            ops[wi*32 + lane] = p;
            __syncthreads();
            if (wi == 0) {
                float o = sm[OFF_BL];
#pragma unroll
                for (int j = 0; j < 8; j++) o += ops[j*32 + lane];
                if (nt == 0) out[(m0 + lane)*Ttot + t] = o;
                if (t >= Tlen - 1) ash[lane] = o;   // x for step t+1 (future phase)
            }
        }
        // step-top __syncthreads orders ash[0..31] before next GEMM
    }
}

extern "C" void kernel_launch(void* const* d_in, const int* in_sizes, int n_in,
                              void* d_out, int out_size)
{
    const float* x    = (const float*)d_in[0];
    const float* Wih1 = (const float*)d_in[1];
    const float* Whh1 = (const float*)d_in[2];
    const float* bih1 = (const float*)d_in[3];
    const float* bhh1 = (const float*)d_in[4];
    const float* Wih2 = (const float*)d_in[5];
    const float* Whh2 = (const float*)d_in[6];
    const float* bih2 = (const float*)d_in[7];
    const float* bhh2 = (const float*)d_in[8];
    const float* Wih3 = (const float*)d_in[9];
    const float* Whh3 = (const float*)d_in[10];
    const float* bih3 = (const float*)d_in[11];
    const float* bhh3 = (const float*)d_in[12];
    const float* Wlin = (const float*)d_in[13];
    const float* blin = (const float*)d_in[14];
    (void)in_sizes; (void)n_in;

    int fut = out_size / Bsz - Tlen;   // derive future length from output shape

    cudaFuncSetAttribute((const void*)lstm_forecast_kernel,
                         cudaFuncAttributeMaxDynamicSharedMemorySize, SMEM_BYTES);

    lstm_forecast_kernel<<<NBLK, NTHR, SMEM_BYTES>>>(
        x, Wih1, Whh1, bih1, bhh1, Wih2, Whh2, bih2, bhh2,
        Wih3, Whh3, bih3, bhh3, Wlin, blin, (float*)d_out, fut);
}

// round 8
// speedup vs baseline: 1.1442x; 1.1442x over previous
#include <cuda_runtime.h>
#include <math.h>

#define Bsz   256
#define Tlen  1024
#define Hdim  128
#define NBLK  128      // 8 batch-tiles x 16 unit-tiles
#define NTHR  256
#define MT    32       // batches per CTA
#define UT    8        // hidden units per CTA (x4 gates = 32 rows)
#define ASTR  386      // activation row stride (even; ==2 mod 32 -> clean LDS.64)

// k2 counts per layer (k padded even; slot map: 0=x, 1=zero, 2..129=h1, 130..257=h2, 258..385=h3)
#define K2_1  65       // layer1: slots [0,130)
#define K2_2  129      // layer2: slots [0,258)
#define K2_3  193      // layer3: slots [0,386)

// ---- shared memory layout (float offsets) ----
#define OFF_W1 0
#define OFF_W2 (OFF_W1 + K2_1*64)       // 4160
#define OFF_W3 (OFF_W2 + K2_2*64)       // 12416
#define OFF_A  (OFF_W3 + K2_3*64)       // 24768  activations [m][slot], stride ASTR
#define OFF_G  (OFF_A  + 32*ASTR)       // 37120  gate partials: 2 x [32 rows][32 m]
#define OFF_C  (OFF_G  + 2048)          // 39168  c state [3][8][32]
#define OFF_BS (OFF_C  + 768)           // 39936  combined biases [3][32]
#define OFF_WL (OFF_BS + 96)            // 40032  W_lin in slot space [388]
#define OFF_OP (OFF_WL + 388)           // 40420  o partials [8][32]
#define OFF_BL (OFF_OP + 256)           // 40676  b_lin
#define SMEM_FLOATS (OFF_BL + 4)        // 40680
#define SMEM_BYTES  (SMEM_FLOATS*4)     // 162720 bytes -> 1 CTA/SM

// ---- global scratch ----
__device__ float    g_h[3][Hdim][Bsz];      // [layer][unit][batch]
__device__ unsigned g_flag[8][3][16];       // [mt][phase][nt], monotonic tokens

// k-pair GEMM range: warp handles rows 8*wg..8*wg+7 over k2 in [A,B).
// acc[q] is f32x2: half0 accumulates even k, half1 odd k, for row 8*wg+q.
template<int A, int B>
__device__ __forceinline__ void gemm_range(const float* __restrict__ wb,
                                           const float* __restrict__ arow,
                                           int wg, unsigned long long* acc)
{
    const float* wp0 = wb + 16*wg;
#pragma unroll 4
    for (int k2 = A; k2 < B; k2++) {
        unsigned long long ap = *reinterpret_cast<const unsigned long long*>(arow + 2*k2);
        const ulonglong2* wq = reinterpret_cast<const ulonglong2*>(wp0 + k2*64);
        ulonglong2 wv0 = wq[0];
        ulonglong2 wv1 = wq[1];
        ulonglong2 wv2 = wq[2];
        ulonglong2 wv3 = wq[3];
        asm("fma.rn.f32x2 %0, %1, %2, %0;" : "+l"(acc[0]) : "l"(ap), "l"(wv0.x));
        asm("fma.rn.f32x2 %0, %1, %2, %0;" : "+l"(acc[1]) : "l"(ap), "l"(wv0.y));
        asm("fma.rn.f32x2 %0, %1, %2, %0;" : "+l"(acc[2]) : "l"(ap), "l"(wv1.x));
        asm("fma.rn.f32x2 %0, %1, %2, %0;" : "+l"(acc[3]) : "l"(ap), "l"(wv1.y));
        asm("fma.rn.f32x2 %0, %1, %2, %0;" : "+l"(acc[4]) : "l"(ap), "l"(wv2.x));
        asm("fma.rn.f32x2 %0, %1, %2, %0;" : "+l"(acc[5]) : "l"(ap), "l"(wv2.y));
        asm("fma.rn.f32x2 %0, %1, %2, %0;" : "+l"(acc[6]) : "l"(ap), "l"(wv3.x));
        asm("fma.rn.f32x2 %0, %1, %2, %0;" : "+l"(acc[7]) : "l"(ap), "l"(wv3.y));
    }
}

// split-k dispatch: warps with kh==0 take [A,MID), kh==1 take [MID,B)
template<int A, int B>
__device__ __forceinline__ void gemm_part(const float* __restrict__ wb,
                                          const float* __restrict__ arow,
                                          int wg, int kh, unsigned long long* acc)
{
    constexpr int MID = A + (B - A) / 2;
    if (kh == 0) gemm_range<A, MID>(wb, arow, wg, acc);
    else         gemm_range<MID, B>(wb, arow, wg, acc);
}

__device__ __forceinline__ void store_gates(float* __restrict__ gdst, int wg, int lane,
                                            const unsigned long long* acc)
{
    float* gp = gdst + (8*wg)*32 + lane;
#pragma unroll
    for (int q = 0; q < 8; q++) {
        float lo, hi;
        asm("mov.b64 {%0, %1}, %2;" : "=f"(lo), "=f"(hi) : "l"(acc[q]));
        gp[q*32] = lo + hi;
    }
}

__device__ __forceinline__ float sigm(float v) { return 1.f / (1.f + __expf(-v)); }

// per (u=warp, m=lane): combine split-k gate partials, update c (SMEM), write h to global
__device__ __forceinline__ void cell_update(int layer, int u, int m, int nt, int m0,
                                            const float* __restrict__ gsh,
                                            const float* __restrict__ bs,
                                            float* __restrict__ csh,
                                            float* __restrict__ hglob)
{
    float xi = gsh[( 0 + u)*32 + m] + gsh[1024 + ( 0 + u)*32 + m] + bs[ 0 + u];
    float xf = gsh[( 8 + u)*32 + m] + gsh[1024 + ( 8 + u)*32 + m] + bs[ 8 + u];
    float xg = gsh[(16 + u)*32 + m] + gsh[1024 + (16 + u)*32 + m] + bs[16 + u];
    float xo = gsh[(24 + u)*32 + m] + gsh[1024 + (24 + u)*32 + m] + bs[24 + u];
    float ii = sigm(xi);
    float ff = sigm(xf);
    float gg = tanhf(xg);
    float oo = sigm(xo);
    float* cp = csh + layer*(UT*32) + u*32 + m;
    float c = ff * cp[0] + ii * gg;
    cp[0] = c;
    hglob[(nt*UT + u)*Bsz + m0 + m] = oo * tanhf(c);
}

__global__ void __launch_bounds__(NTHR, 1)
lstm_forecast_kernel(const float* __restrict__ x,
                     const float* __restrict__ Wih1, const float* __restrict__ Whh1,
                     const float* __restrict__ bih1, const float* __restrict__ bhh1,
                     const float* __restrict__ Wih2, const float* __restrict__ Whh2,
                     const float* __restrict__ bih2, const float* __restrict__ bhh2,
                     const float* __restrict__ Wih3, const float* __restrict__ Whh3,
                     const float* __restrict__ bih3, const float* __restrict__ bhh3,
                     const float* __restrict__ Wlin, const float* __restrict__ blin,
                     float* __restrict__ out, int fut)
{
    extern __shared__ float sm[];
    const int tid  = threadIdx.x;
    const int lane = tid & 31;
    const int wi   = tid >> 5;
    const int wg   = wi & 3;            // row octet within split-k group
    const int kh   = wi >> 2;           // k-half (0: low, 1: high)
    const int mt   = blockIdx.x >> 4;   // 0..7  batch tile
    const int nt   = blockIdx.x & 15;   // 0..15 unit tile
    const int m0   = mt * MT;

    float* w1  = sm + OFF_W1;
    float* w2p = sm + OFF_W2;
    float* w3p = sm + OFF_W3;
    float* ash = sm + OFF_A;
    float* gsh = sm + OFF_G;
    float* csh = sm + OFF_C;
    float* bsh = sm + OFF_BS;
    float* wls = sm + OFF_WL;
    float* ops = sm + OFF_OP;

    // ---------------- prologue: pack weight slices into slot/k-pair layout ----------------
    // slot map: 0=x, 1=zero, 2..129=h1, 130..257=h2, 258..385=h3
    // w layout per layer: w[k2*64 + r*2 + j], (r local row, j in {0,1}, slot = 2*k2+j)
    for (int idx = tid; idx < K2_1*64; idx += NTHR) {
        int k2 = idx >> 6, rj = idx & 63, r = rj >> 1, j = rj & 1, s = 2*k2 + j;
        int rg = ((r >> 3) << 7) + nt*UT + (r & 7);
        float v = (s == 1) ? 0.f : ((s == 0) ? Wih1[rg] : Whh1[rg*Hdim + (s - 2)]);
        w1[idx] = v;
    }
    for (int idx = tid; idx < K2_2*64; idx += NTHR) {
        int k2 = idx >> 6, rj = idx & 63, r = rj >> 1, j = rj & 1, s = 2*k2 + j;
        int rg = ((r >> 3) << 7) + nt*UT + (r & 7);
        float v;
        if (s == 1)        v = 0.f;
        else if (s == 0)   v = Wih2[rg*129];
        else if (s < 130)  v = Wih2[rg*129 + (s - 1)];
        else               v = Whh2[rg*Hdim + (s - 130)];
        w2p[idx] = v;
    }
    for (int idx = tid; idx < K2_3*64; idx += NTHR) {
        int k2 = idx >> 6, rj = idx & 63, r = rj >> 1, j = rj & 1, s = 2*k2 + j;
        int rg = ((r >> 3) << 7) + nt*UT + (r & 7);
        float v;
        if (s == 1)        v = 0.f;
        else if (s == 0)   v = Wih3[rg*257];
        else if (s < 258)  v = Wih3[rg*257 + (s - 1)];
        else               v = Whh3[rg*Hdim + (s - 258)];
        w3p[idx] = v;
    }
    if (tid < 32) {
        int r = tid;
        int rg = ((r >> 3) << 7) + nt*UT + (r & 7);
        bsh[0*32 + r] = bih1[rg] + bhh1[rg];
        bsh[1*32 + r] = bih2[rg] + bhh2[rg];
        bsh[2*32 + r] = bih3[rg] + bhh3[rg];
    }
    for (int s = tid; s < 388; s += NTHR)
        wls[s] = (s >= 386 || s == 1) ? 0.f : ((s == 0) ? Wlin[0] : Wlin[s - 1]);
    if (tid == 0) sm[OFF_BL] = blin[0];
    for (int idx = tid; idx < 32*ASTR; idx += NTHR) ash[idx] = 0.f;  // h(-1)=0, pad slot stays 0
    for (int idx = tid; idx < 3*UT*32; idx += NTHR) csh[idx] = 0.f;

    // replay-safe barrier base: own flag's entry value (all flags equal at launch entry)
    const unsigned base = *(volatile unsigned*)&g_flag[mt][0][nt];
    __syncthreads();

    const int Ttot = Tlen + fut;
    const int u = wi;      // cell-update mapping (unit, batch-lane)
    const int m = lane;
    const float* arow = ash + lane*ASTR;
    const float blv = sm[OFF_BL];

    float xv = 0.f;
    if (tid < 32) xv = x[(m0 + tid)*Tlen + 0];

    for (int t = 0; t < Ttot; t++) {
        const unsigned tok0 = base + 3u*t + 1u;
        const unsigned tok1 = tok0 + 1u;
        const unsigned tok2 = tok0 + 2u;

        // x slot (future phase: already holds fed-back o); prefetch next x
        if (t < Tlen && tid < 32) ash[tid*ASTR] = xv;
        if (tid < 32 && t + 1 < Tlen) xv = x[(m0 + tid)*Tlen + (t + 1)];
        __syncthreads();

        // ---------- layer 1 (x + h1_prev: fully local) ----------
        {
            unsigned long long acc[8] = {0,0,0,0,0,0,0,0};
            gemm_part<0, K2_1>(w1, arow, wg, kh, acc);
            store_gates(gsh + kh*1024, wg, lane, acc);
        }
        __syncthreads();
        cell_update(0, u, m, nt, m0, gsh, bsh + 0, csh, &g_h[0][0][0]);
        __threadfence();
        __syncthreads();
        if (tid == 0) *(volatile unsigned*)&g_flag[mt][0][nt] = tok0;

        // overlap barrier0 wait with recurrent partials (h2_prev, h3_prev)
        unsigned long long acc2[8] = {0,0,0,0,0,0,0,0};
        unsigned long long acc3[8] = {0,0,0,0,0,0,0,0};
        gemm_part<K2_1, K2_2>(w2p, arow, wg, kh, acc2);   // W_hh2 * h2(t-1)
        gemm_part<K2_2, K2_3>(w3p, arow, wg, kh, acc3);   // W_hh3 * h3(t-1)

        if (tid < 16) {   // spin barrier0
            volatile unsigned* p = &g_flag[mt][0][tid];
            while ((int)(*p - tok0) < 0) { }
            __threadfence();
        }
        __syncthreads();
        {   // refresh h1 -> slots 2..129
            const float* hg = &g_h[0][0][0];
            for (int i = tid; i < Hdim*32; i += NTHR)
                ash[(i & 31)*ASTR + 2 + (i >> 5)] = __ldcg(hg + (i >> 5)*Bsz + m0 + (i & 31));
        }
        __syncthreads();

        // ---------- layer 2 finish (x + fresh h1) ----------
        gemm_part<0, K2_1>(w2p, arow, wg, kh, acc2);
        store_gates(gsh + kh*1024, wg, lane, acc2);
        __syncthreads();
        cell_update(1, u, m, nt, m0, gsh, bsh + 32, csh, &g_h[1][0][0]);
        __threadfence();
        __syncthreads();
        if (tid == 0) *(volatile unsigned*)&g_flag[mt][1][nt] = tok1;

        // overlap barrier1 wait with layer3 (x + h1) partial
        gemm_part<0, K2_1>(w3p, arow, wg, kh, acc3);

        if (tid < 16) {   // spin barrier1
            volatile unsigned* p = &g_flag[mt][1][tid];
            while ((int)(*p - tok1) < 0) { }
            __threadfence();
        }
        __syncthreads();
        {   // refresh h2 -> slots 130..257
            const float* hg = &g_h[1][0][0];
            for (int i = tid; i < Hdim*32; i += NTHR)
                ash[(i & 31)*ASTR + 130 + (i >> 5)] = __ldcg(hg + (i >> 5)*Bsz + m0 + (i & 31));
        }
        __syncthreads();

        // ---------- layer 3 finish (fresh h2) ----------
        gemm_part<K2_1, K2_2>(w3p, arow, wg, kh, acc3);
        store_gates(gsh + kh*1024, wg, lane, acc3);
        __syncthreads();
        cell_update(2, u, m, nt, m0, gsh, bsh + 64, csh, &g_h[2][0][0]);
        __threadfence();
        __syncthreads();
        if (tid == 0) *(volatile unsigned*)&g_flag[mt][2][nt] = tok2;

        // ---------- linear head ----------
        const bool doo = (nt == 0) || (t >= Tlen - 1);
        float p = 0.f;
        if (doo) {   // partial over slots [0,256): x, h1, h2 (all fresh) — overlaps barrier2
            for (int k = wi; k < 256; k += 8) p = fmaf(wls[k], arow[k], p);
        }

        if (tid < 16) {   // spin barrier2
            volatile unsigned* q = &g_flag[mt][2][tid];
            while ((int)(*q - tok2) < 0) { }
            __threadfence();
        }
        __syncthreads();
        {   // refresh h3 -> slots 258..385 (needed for o and next step's recurrent partial)
            const float* hg = &g_h[2][0][0];
            for (int i = tid; i < Hdim*32; i += NTHR)
                ash[(i & 31)*ASTR + 258 + (i >> 5)] = __ldcg(hg + (i >> 5)*Bsz + m0 + (i & 31));
        }
        __syncthreads();

        if (doo) {
            for (int k = 256 + wi; k < 386; k += 8) p = fmaf(wls[k], arow[k], p);
            ops[wi*32 + lane] = p;
            __syncthreads();
            if (wi == 0) {
                float o = blv;
#pragma unroll
                for (int j = 0; j < 8; j++) o += ops[j*32 + lane];
                if (nt == 0) out[(m0 + lane)*Ttot + t] = o;
                if (t >= Tlen - 1) ash[lane*ASTR] = o;   // feed back as next x
            }
        }
        // loop-top __syncthreads orders the feedback write before next step's GEMM
    }
}

extern "C" void kernel_launch(void* const* d_in, const int* in_sizes, int n_in,
                              void* d_out, int out_size)
{
    const float* x    = (const float*)d_in[0];
    const float* Wih1 = (const float*)d_in[1];
    const float* Whh1 = (const float*)d_in[2];
    const float* bih1 = (const float*)d_in[3];
    const float* bhh1 = (const float*)d_in[4];
    const float* Wih2 = (const float*)d_in[5];
    const float* Whh2 = (const float*)d_in[6];
    const float* bih2 = (const float*)d_in[7];
    const float* bhh2 = (const float*)d_in[8];
    const float* Wih3 = (const float*)d_in[9];
    const float* Whh3 = (const float*)d_in[10];
    const float* bih3 = (const float*)d_in[11];
    const float* bhh3 = (const float*)d_in[12];
    const float* Wlin = (const float*)d_in[13];
    const float* blin = (const float*)d_in[14];
    (void)in_sizes; (void)n_in;

    int fut = out_size / Bsz - Tlen;

    cudaFuncSetAttribute((const void*)lstm_forecast_kernel,
                         cudaFuncAttributeMaxDynamicSharedMemorySize, SMEM_BYTES);

    lstm_forecast_kernel<<<NBLK, NTHR, SMEM_BYTES>>>(
        x, Wih1, Whh1, bih1, bhh1, Wih2, Whh2, bih2, bhh2,
        Wih3, Whh3, bih3, bhh3, Wlin, blin, (float*)d_out, fut);
}

// round 9
// speedup vs baseline: 1.5743x; 1.3759x over previous
#include <cuda_runtime.h>
#include <math.h>

#define Bsz   256
#define Tlen  1024
#define Hdim  128
#define NBLK  128      // 8 batch-tiles x 16 unit-tiles
#define NTHR  256
#define MT    32       // batches per CTA
#define UT    8        // hidden units per CTA (x4 gates = 32 rows)
#define ASTR  386      // activation row stride (even; ASTR/2 odd -> conflict-free LDS.64)

// k2 (k-pair) bounds; slot map: 0=x, 1=zero, 2..129=h1, 130..257=h2, 258..385=h3
#define K2_1  65       // x+h1 part: k2 [0,65)
#define K2_2  129      // + h2 part: k2 [65,129)
#define K2_3  193      // + h3 part: k2 [129,193)

// ---- shared memory layout (float offsets) ----
#define OFF_W1 0
#define OFF_W2 (OFF_W1 + K2_1*64)       // 4160
#define OFF_W3 (OFF_W2 + K2_2*64)       // 12416
#define OFF_A  (OFF_W3 + K2_3*64)       // 24768  activations [m][slot], stride ASTR
#define OFF_G  (OFF_A  + 32*ASTR)       // 37120  gate partials: 4 x [32 rows][32 m]
#define OFF_C  (OFF_G  + 4096)          // 41216  c state [3][8][32]
#define OFF_BS (OFF_C  + 768)           // 41984  combined biases [3][32]
#define OFF_WL (OFF_BS + 96)            // 42080  W_lin in slot space [388]
#define OFF_OP (OFF_WL + 388)           // 42468  o partials [8][32]
#define OFF_BL (OFF_OP + 256)           // 42724  b_lin
#define SMEM_FLOATS (OFF_BL + 4)        // 42728
#define SMEM_BYTES  (SMEM_FLOATS*4)     // 170912 bytes -> 1 CTA/SM

// ---- global scratch ----
__device__ __align__(256) float g_h[3][Hdim][Bsz];   // [layer][unit][batch]
__device__ unsigned g_flag[8][3][16][32];            // padded: one 128B line per flag

__device__ __forceinline__ unsigned ld_acq(const unsigned* p) {
    unsigned v;
    asm volatile("ld.acquire.gpu.u32 %0, [%1];" : "=r"(v) : "l"(p) : "memory");
    return v;
}
__device__ __forceinline__ void st_rel(unsigned* p, unsigned v) {
    asm volatile("st.release.gpu.u32 [%0], %1;" :: "l"(p), "r"(v) : "memory");
}

// 16-row x 32-batch x [lo,hi) k2 GEMM. Warp rg2 owns rows 16*rg2..16*rg2+15.
// acc[q] is f32x2 (even-k half, odd-k half) for row 16*rg2+q.
__device__ __forceinline__ void gemm16(const float* __restrict__ wb,
                                       const float* __restrict__ arow,
                                       int rg2, int lo, int hi,
                                       unsigned long long* __restrict__ acc)
{
    const char* wp = (const char*)(wb + rg2*32);
#pragma unroll 2
    for (int k2 = lo; k2 < hi; k2++) {
        unsigned long long ap = *(const unsigned long long*)(arow + 2*k2);
        const ulonglong2* w = (const ulonglong2*)(wp + (size_t)k2*256);
#pragma unroll
        for (int q = 0; q < 4; q++) {
            ulonglong2 w0 = w[2*q];
            ulonglong2 w1 = w[2*q+1];
            asm("fma.rn.f32x2 %0, %1, %2, %0;" : "+l"(acc[4*q+0]) : "l"(ap), "l"(w0.x));
            asm("fma.rn.f32x2 %0, %1, %2, %0;" : "+l"(acc[4*q+1]) : "l"(ap), "l"(w0.y));
            asm("fma.rn.f32x2 %0, %1, %2, %0;" : "+l"(acc[4*q+2]) : "l"(ap), "l"(w1.x));
            asm("fma.rn.f32x2 %0, %1, %2, %0;" : "+l"(acc[4*q+3]) : "l"(ap), "l"(w1.y));
        }
    }
}

__device__ __forceinline__ void store_gates16(float* __restrict__ gsh, int kq, int rg2, int lane,
                                              const unsigned long long* __restrict__ acc)
{
    float* gp = gsh + kq*1024 + (rg2*16)*32 + lane;
#pragma unroll
    for (int q = 0; q < 16; q++) {
        float lo, hi;
        asm("mov.b64 {%0, %1}, %2;" : "=f"(lo), "=f"(hi) : "l"(acc[q]));
        gp[q*32] = lo + hi;
    }
}

__device__ __forceinline__ float sigm(float v) {
    return __fdividef(1.f, 1.f + __expf(-v));
}
__device__ __forceinline__ float tanh_fast(float v) {
    return 1.f - __fdividef(2.f, __expf(2.f*v) + 1.f);   // exact at saturation
}

// combine 4 split-k partials + bias, update c (SMEM), write h to global L2
__device__ __forceinline__ void cell_update(int layer, int u, int m, int nt, int m0,
                                            const float* __restrict__ gsh,
                                            const float* __restrict__ bs,
                                            float* __restrict__ csh,
                                            float* __restrict__ hglob)
{
#define GSUM(r) (gsh[(r)*32+m] + gsh[1024+(r)*32+m] + gsh[2048+(r)*32+m] + gsh[3072+(r)*32+m])
    float xi = GSUM( 0 + u) + bs[ 0 + u];
    float xf = GSUM( 8 + u) + bs[ 8 + u];
    float xg = GSUM(16 + u) + bs[16 + u];
    float xo = GSUM(24 + u) + bs[24 + u];
#undef GSUM
    float ii = sigm(xi);
    float ff = sigm(xf);
    float gg = tanh_fast(xg);
    float oo = sigm(xo);
    float* cp = csh + layer*(UT*32) + u*32 + m;
    float c = ff * cp[0] + ii * gg;
    cp[0] = c;
    hglob[(nt*UT + u)*Bsz + m0 + m] = oo * tanh_fast(c);
}

// fused spin + refresh: warp wi waits for producers {2wi, 2wi+1} and pulls their
// 8-unit x 32-batch h slices into ash slots [sbase + 8p .. ).
__device__ __forceinline__ void wait_refresh(int mt, int ph, unsigned tok, int wi, int lane,
                                             const float* __restrict__ hg,
                                             float* __restrict__ ash, int sbase, int m0)
{
#pragma unroll
    for (int j = 0; j < 2; j++) {
        int p = 2*wi + j;
        const unsigned* fp = &g_flag[mt][ph][p][0];
        unsigned v;
        do { v = ld_acq(fp); } while ((int)(v - tok) < 0);
#pragma unroll
        for (int i = 0; i < 2; i++) {
            int fidx = i*32 + lane;          // 0..63
            int u    = fidx >> 3;            // 0..7
            int b4   = (fidx & 7) * 4;
            float4 hv = __ldcg((const float4*)(hg + (p*8 + u)*Bsz + m0 + b4));
            float* dst = ash + sbase + p*8 + u;
            dst[(b4+0)*ASTR] = hv.x;
            dst[(b4+1)*ASTR] = hv.y;
            dst[(b4+2)*ASTR] = hv.z;
            dst[(b4+3)*ASTR] = hv.w;
        }
    }
}

__global__ void __launch_bounds__(NTHR, 1)
lstm_forecast_kernel(const float* __restrict__ x,
                     const float* __restrict__ Wih1, const float* __restrict__ Whh1,
                     const float* __restrict__ bih1, const float* __restrict__ bhh1,
                     const float* __restrict__ Wih2, const float* __restrict__ Whh2,
                     const float* __restrict__ bih2, const float* __restrict__ bhh2,
                     const float* __restrict__ Wih3, const float* __restrict__ Whh3,
                     const float* __restrict__ bih3, const float* __restrict__ bhh3,
                     const float* __restrict__ Wlin, const float* __restrict__ blin,
                     float* __restrict__ out, int fut)
{
    extern __shared__ float sm[];
    const int tid  = threadIdx.x;
    const int lane = tid & 31;
    const int wi   = tid >> 5;
    const int rg2  = wi & 1;            // row group: rows 16*rg2 .. +15
    const int kq   = wi >> 1;           // k-quarter 0..3
    const int mt   = blockIdx.x >> 4;   // batch tile 0..7
    const int nt   = blockIdx.x & 15;   // unit tile 0..15
    const int m0   = mt * MT;

    float* w1  = sm + OFF_W1;
    float* w2p = sm + OFF_W2;
    float* w3p = sm + OFF_W3;
    float* ash = sm + OFF_A;
    float* gsh = sm + OFF_G;
    float* csh = sm + OFF_C;
    float* bsh = sm + OFF_BS;
    float* wls = sm + OFF_WL;
    float* ops = sm + OFF_OP;

    // ---------------- prologue: pack weight slices [k2][row*2+j] ----------------
    for (int idx = tid; idx < K2_1*64; idx += NTHR) {
        int k2 = idx >> 6, rj = idx & 63, r = rj >> 1, j = rj & 1, s = 2*k2 + j;
        int rg = ((r >> 3) << 7) + nt*UT + (r & 7);
        w1[idx] = (s == 1) ? 0.f : ((s == 0) ? Wih1[rg] : Whh1[rg*Hdim + (s - 2)]);
    }
    for (int idx = tid; idx < K2_2*64; idx += NTHR) {
        int k2 = idx >> 6, rj = idx & 63, r = rj >> 1, j = rj & 1, s = 2*k2 + j;
        int rg = ((r >> 3) << 7) + nt*UT + (r & 7);
        float v;
        if (s == 1)        v = 0.f;
        else if (s == 0)   v = Wih2[rg*129];
        else if (s < 130)  v = Wih2[rg*129 + (s - 1)];
        else               v = Whh2[rg*Hdim + (s - 130)];
        w2p[idx] = v;
    }
    for (int idx = tid; idx < K2_3*64; idx += NTHR) {
        int k2 = idx >> 6, rj = idx & 63, r = rj >> 1, j = rj & 1, s = 2*k2 + j;
        int rg = ((r >> 3) << 7) + nt*UT + (r & 7);
        float v;
        if (s == 1)        v = 0.f;
        else if (s == 0)   v = Wih3[rg*257];
        else if (s < 258)  v = Wih3[rg*257 + (s - 1)];
        else               v = Whh3[rg*Hdim + (s - 258)];
        w3p[idx] = v;
    }
    if (tid < 32) {
        int r = tid;
        int rg = ((r >> 3) << 7) + nt*UT + (r & 7);
        bsh[0*32 + r] = bih1[rg] + bhh1[rg];
        bsh[1*32 + r] = bih2[rg] + bhh2[rg];
        bsh[2*32 + r] = bih3[rg] + bhh3[rg];
    }
    for (int s = tid; s < 388; s += NTHR)
        wls[s] = (s >= 386 || s == 1) ? 0.f : ((s == 0) ? Wlin[0] : Wlin[s - 1]);
    if (tid == 0) sm[OFF_BL] = blin[0];
    for (int idx = tid; idx < 32*ASTR; idx += NTHR) ash[idx] = 0.f;   // h(-1)=0, pad=0
    for (int idx = tid; idx < 3*UT*32; idx += NTHR) csh[idx] = 0.f;

    // replay-safe token base (all flags equal at launch entry; only we write ours)
    const unsigned base = ld_acq(&g_flag[mt][0][nt][0]);
    __syncthreads();

    const int Ttot = Tlen + fut;
    const int u = wi;        // cell-update mapping (unit = warp, batch = lane)
    const int m = lane;
    const float* arow = ash + lane*ASTR;
    const float blv = sm[OFF_BL];

    // per-warp k2 quarter bounds
    const int xlo = (K2_1*kq) >> 2, xhi = (K2_1*(kq+1)) >> 2;   // x+h1 part [0,65)
    const int r2lo = K2_1 + 16*kq, r2hi = r2lo + 16;            // h2 part  [65,129)
    const int r3lo = K2_2 + 16*kq, r3hi = r3lo + 16;            // h3 part  [129,193)

    float xv = 0.f;
    if (tid < 32) xv = x[(m0 + tid)*Tlen + 0];

    for (int t = 0; t < Ttot; t++) {
        const unsigned tok0 = base + 3u*(unsigned)t + 1u;
        const unsigned tok1 = tok0 + 1u;
        const unsigned tok2 = tok0 + 2u;

        if (t < Tlen && tid < 32) ash[tid*ASTR] = xv;              // x slot
        if (tid < 32 && t + 1 < Tlen) xv = x[(m0 + tid)*Tlen + (t + 1)];
        __syncthreads();

        // ---------- layer 1 (x + h1(t-1): local) ----------
        {
            unsigned long long acc[16] = {0,0,0,0,0,0,0,0,0,0,0,0,0,0,0,0};
            gemm16(w1, arow, rg2, xlo, xhi, acc);
            store_gates16(gsh, kq, rg2, lane, acc);
        }
        __syncthreads();
        cell_update(0, u, m, nt, m0, gsh, bsh + 0, csh, &g_h[0][0][0]);
        __syncthreads();
        if (tid == 0) st_rel(&g_flag[mt][0][nt][0], tok0);

        // overlap barrier0: recurrent partials on stale h2(t-1), h3(t-1)
        unsigned long long acc2[16] = {0,0,0,0,0,0,0,0,0,0,0,0,0,0,0,0};
        unsigned long long acc3[16] = {0,0,0,0,0,0,0,0,0,0,0,0,0,0,0,0};
        gemm16(w2p, arow, rg2, r2lo, r2hi, acc2);   // W_hh2 . h2(t-1)
        gemm16(w3p, arow, rg2, r3lo, r3hi, acc3);   // W_hh3 . h3(t-1)

        wait_refresh(mt, 0, tok0, wi, lane, &g_h[0][0][0], ash, 2, m0);    // h1(t) -> slots 2..129
        __syncthreads();

        // ---------- layer 2 finish (x + fresh h1) ----------
        gemm16(w2p, arow, rg2, xlo, xhi, acc2);
        store_gates16(gsh, kq, rg2, lane, acc2);
        __syncthreads();
        cell_update(1, u, m, nt, m0, gsh, bsh + 32, csh, &g_h[1][0][0]);
        __syncthreads();
        if (tid == 0) st_rel(&g_flag[mt][1][nt][0], tok1);

        // overlap barrier1: layer3's x+h1 part
        gemm16(w3p, arow, rg2, xlo, xhi, acc3);

        wait_refresh(mt, 1, tok1, wi, lane, &g_h[1][0][0], ash, 130, m0);  // h2(t) -> slots 130..257
        __syncthreads();

        // ---------- layer 3 finish (fresh h2) ----------
        gemm16(w3p, arow, rg2, r2lo, r2hi, acc3);
        store_gates16(gsh, kq, rg2, lane, acc3);
        __syncthreads();
        cell_update(2, u, m, nt, m0, gsh, bsh + 64, csh, &g_h[2][0][0]);
        __syncthreads();
        if (tid == 0) st_rel(&g_flag[mt][2][nt][0], tok2);

        // ---------- linear head ----------
        const bool doo = (nt == 0) || (t >= Tlen - 1);
        float p = 0.f;
        if (doo) {   // slots [0,256): x, h1, h2 all fresh — overlaps barrier2
            for (int k = wi; k < 256; k += 8) p = fmaf(wls[k], arow[k], p);
        }

        wait_refresh(mt, 2, tok2, wi, lane, &g_h[2][0][0], ash, 258, m0);  // h3(t) -> slots 258..385
        __syncthreads();

        if (doo) {
            for (int k = 256 + wi; k < 386; k += 8) p = fmaf(wls[k], arow[k], p);
            ops[wi*32 + lane] = p;
            __syncthreads();
            if (wi == 0) {
                float o = blv;
#pragma unroll
                for (int j = 0; j < 8; j++) o += ops[j*32 + lane];
                if (nt == 0) out[(m0 + lane)*Ttot + t] = o;
                if (t >= Tlen - 1) ash[lane*ASTR] = o;   // feed back as next x
            }
        }
        // loop-top __syncthreads orders feedback write before next step's GEMM
    }
}

extern "C" void kernel_launch(void* const* d_in, const int* in_sizes, int n_in,
                              void* d_out, int out_size)
{
    const float* x    = (const float*)d_in[0];
    const float* Wih1 = (const float*)d_in[1];
    const float* Whh1 = (const float*)d_in[2];
    const float* bih1 = (const float*)d_in[3];
    const float* bhh1 = (const float*)d_in[4];
    const float* Wih2 = (const float*)d_in[5];
    const float* Whh2 = (const float*)d_in[6];
    const float* bih2 = (const float*)d_in[7];
    const float* bhh2 = (const float*)d_in[8];
    const float* Wih3 = (const float*)d_in[9];
    const float* Whh3 = (const float*)d_in[10];
    const float* bih3 = (const float*)d_in[11];
    const float* bhh3 = (const float*)d_in[12];
    const float* Wlin = (const float*)d_in[13];
    const float* blin = (const float*)d_in[14];
    (void)in_sizes; (void)n_in;

    int fut = out_size / Bsz - Tlen;

    cudaFuncSetAttribute((const void*)lstm_forecast_kernel,
                         cudaFuncAttributeMaxDynamicSharedMemorySize, SMEM_BYTES);

    lstm_forecast_kernel<<<NBLK, NTHR, SMEM_BYTES>>>(
        x, Wih1, Whh1, bih1, bhh1, Wih2, Whh2, bih2, bhh2,
        Wih3, Whh3, bih3, bhh3, Wlin, blin, (float*)d_out, fut);
}